// round 10
// baseline (speedup 1.0000x reference)
#include <cuda_runtime.h>

#define N_NODES  20000
#define N_EDGES  320000
#define F_EDGE   32
#define D_IN     16
#define D_NN     16
#define D_GAT    64
#define HID      128
#define N_GRAPHS 64
#define NEG_SLOPE 0.2f

// ---------------- scratch (zero-initialized at load; hist self-cleaned by k_scan) ----------------
static __device__ __align__(16) float g_WeT[F_EDGE * D_IN * D_NN];   // WeT[f][o][i]
static __device__ __align__(16) float g_agg[N_NODES * D_NN];
static __device__ __align__(16) float g_hp[N_NODES * D_GAT];
static __device__ __align__(16) float g_pooled[N_GRAPHS * D_GAT];
static __device__ float g_scs[N_NODES];
static __device__ float g_scd[N_NODES];
static __device__ float g_eself[N_NODES];
static __device__ float g_selfw[N_NODES];
static __device__ float g_invden[N_NODES];
static __device__ float g_cnt[N_GRAPHS];
// sorting scratch
static __device__ int g_hist_src[N_NODES], g_hist_dst[N_NODES];
static __device__ int g_rp_src[N_NODES + 1], g_rp_dst[N_NODES + 1];
static __device__ int g_cur_src[N_NODES], g_cur_dst[N_NODES];
static __device__ __align__(8) int2 g_se_ed[N_EDGES];  // by-src order: (edge id, dst)
static __device__ int g_de_s[N_EDGES];                 // by-dst order: src ids
static __device__ float g_ev[N_EDGES];                 // softmax buffer

// ---------------- helpers ----------------
__device__ __forceinline__ void red_add_v4(float* p, float4 v) {
    asm volatile("red.global.add.v4.f32 [%0], {%1,%2,%3,%4};"
                 :: "l"(p), "f"(v.x), "f"(v.y), "f"(v.z), "f"(v.w) : "memory");
}
__device__ __forceinline__ void red_add_f32(float* p, float v) {
    asm volatile("red.global.add.f32 [%0], %1;" :: "l"(p), "f"(v) : "memory");
}
__device__ __forceinline__ float lrelu(float v) { return v > 0.f ? v : NEG_SLOPE * v; }

// ---------------- K0: histograms + WeT transpose + zero accumulators (fused) ----------------
// g_hist_* must be zero at entry: guaranteed at load, and k_scan re-zeroes after reading.
__global__ void k_hist(const int* __restrict__ ei, const float* __restrict__ We) {
    int t = blockIdx.x * blockDim.x + threadIdx.x;
    int stride = gridDim.x * blockDim.x;
    for (int i = t; i < F_EDGE * D_IN * D_NN; i += stride) {
        int f = i >> 8, r = i & 255, o = r >> 4, ii = r & 15;
        g_WeT[(f << 8) + (o << 4) + ii] = We[(f << 8) + (ii << 4) + o];
    }
    for (int i = t; i < N_NODES * D_NN; i += stride) g_agg[i] = 0.f;
    for (int i = t; i < N_GRAPHS * D_GAT; i += stride) g_pooled[i] = 0.f;
    for (int i = t; i < N_GRAPHS; i += stride) g_cnt[i] = 0.f;
    for (int e = t; e < N_EDGES; e += stride) {
        atomicAdd(&g_hist_src[ei[e]], 1);
        atomicAdd(&g_hist_dst[ei[N_EDGES + e]], 1);
    }
}

// ---------------- K1: exclusive scan of both histograms (shfl-based, self-cleans hist) ----------------
#define SCAN_CHUNK 20
__global__ void k_scan() {
    int* hist = (blockIdx.x == 0) ? g_hist_src : g_hist_dst;
    int* rp   = (blockIdx.x == 0) ? g_rp_src   : g_rp_dst;
    int* cur  = (blockIdx.x == 0) ? g_cur_src  : g_cur_dst;
    __shared__ int wsum[32];
    int tid = threadIdx.x;
    int lane = tid & 31, wid = tid >> 5;
    int base = tid * SCAN_CHUNK;
    int local[SCAN_CHUNK];
    int s = 0;
#pragma unroll
    for (int k = 0; k < SCAN_CHUNK; k++) {
        int idx = base + k;
        int v = 0;
        if (idx < N_NODES) { v = hist[idx]; hist[idx] = 0; }   // read + self-clean
        local[k] = s; s += v;
    }
    // warp-level inclusive scan of per-thread sums
    int sc = s;
#pragma unroll
    for (int off = 1; off < 32; off <<= 1) {
        int tv = __shfl_up_sync(0xffffffffu, sc, off);
        if (lane >= off) sc += tv;
    }
    if (lane == 31) wsum[wid] = sc;
    __syncthreads();
    if (wid == 0) {
        int v = wsum[lane];
#pragma unroll
        for (int off = 1; off < 32; off <<= 1) {
            int tv = __shfl_up_sync(0xffffffffu, v, off);
            if (lane >= off) v += tv;
        }
        wsum[lane] = v;
    }
    __syncthreads();
    int offset = sc - s + (wid > 0 ? wsum[wid - 1] : 0);   // exclusive prefix of this thread
#pragma unroll
    for (int k = 0; k < SCAN_CHUNK; k++) {
        int idx = base + k;
        if (idx < N_NODES) { rp[idx] = offset + local[k]; cur[idx] = offset + local[k]; }
    }
    if (tid == 1023) rp[N_NODES] = offset + s;
}

// ---------------- K2: scatter into both sorted orders (2 edges/thread for ILP) ----------------
__global__ void k_scatter(const int* __restrict__ ei) {
    int t = blockIdx.x * blockDim.x + threadIdx.x;
    int e0 = 2 * t, e1 = 2 * t + 1;
    if (e0 >= N_EDGES) return;
    int s0 = ei[e0], d0 = ei[N_EDGES + e0];
    int s1 = 0, d1 = 0;
    bool has1 = (e1 < N_EDGES);
    if (has1) { s1 = ei[e1]; d1 = ei[N_EDGES + e1]; }
    int p0 = atomicAdd(&g_cur_src[s0], 1);
    int q0 = atomicAdd(&g_cur_dst[d0], 1);
    int p1 = 0, q1 = 0;
    if (has1) {
        p1 = atomicAdd(&g_cur_src[s1], 1);
        q1 = atomicAdd(&g_cur_dst[d1], 1);
    }
    g_se_ed[p0] = make_int2(e0, d0);
    g_de_s[q0] = s0;
    if (has1) {
        g_se_ed[p1] = make_int2(e1, d1);
        g_de_s[q1] = s1;
    }
}

// ---------------- K3 (profiled slot): NNConv — warp per 2 src nodes, X2 register-resident ----------------
#define EA_CHUNK 8
__global__ void k_nnconv(const float* __restrict__ x, const float* __restrict__ ea) {
    __shared__ __align__(16) float s_ea[8][EA_CHUNK][F_EDGE];   // 8 KB
    int w = (blockIdx.x * blockDim.x + threadIdx.x) >> 5;  // warp id < 10000
    int wl = threadIdx.x >> 5;
    int lane = threadIdx.x & 31;
    int g = lane >> 4, o = lane & 15;

    int n0 = 2 * w, n1 = 2 * w + 1;
    float X2a[16], X2b[16];
    {
        float4 xa[4], xb[4];
#pragma unroll
        for (int c = 0; c < 4; c++) {
            xa[c] = *reinterpret_cast<const float4*>(&x[n0 * D_IN + c * 4]);
            xb[c] = *reinterpret_cast<const float4*>(&x[n1 * D_IN + c * 4]);
        }
#pragma unroll
        for (int k = 0; k < 16; k++) {
            const float4* wt = reinterpret_cast<const float4*>(
                &g_WeT[((16 * g + k) << 8) + (o << 4)]);
            float sa = 0.f, sb = 0.f;
#pragma unroll
            for (int c = 0; c < 4; c++) {
                float4 wv = wt[c];
                sa += xa[c].x * wv.x + xa[c].y * wv.y + xa[c].z * wv.z + xa[c].w * wv.w;
                sb += xb[c].x * wv.x + xb[c].y * wv.y + xb[c].z * wv.z + xb[c].w * wv.w;
            }
            X2a[k] = sa; X2b[k] = sb;
        }
    }

#pragma unroll
    for (int half = 0; half < 2; half++) {
        int n = half ? n1 : n0;
        int beg = g_rp_src[n], end = g_rp_src[n + 1];
        for (int base = beg; base < end; base += EA_CHUNK) {
            int nleft = min(EA_CHUNK, end - base);
            // stage ea rows for up to 8 edges (2 coalesced rounds)
#pragma unroll
            for (int r = 0; r < 2; r++) {
                int item = lane + 32 * r;         // 0..63
                int i = item >> 3, c = item & 7;
                if (i < nleft) {
                    int e = g_se_ed[base + i].x;
                    *reinterpret_cast<float4*>(&s_ea[wl][i][c * 4]) =
                        *reinterpret_cast<const float4*>(&ea[(size_t)e * F_EDGE + c * 4]);
                }
            }
            __syncwarp();
#pragma unroll 2
            for (int i = 0; i < nleft; i++) {
                int d = g_se_ed[base + i].y;   // broadcast, L1-hot
                const float4* ar = reinterpret_cast<const float4*>(&s_ea[wl][i][g * 16]);
                float4 a0 = ar[0], a1 = ar[1], a2 = ar[2], a3 = ar[3];
                float p;
                if (half == 0) {
                    p = a0.x * X2a[0]  + a0.y * X2a[1]  + a0.z * X2a[2]  + a0.w * X2a[3]
                      + a1.x * X2a[4]  + a1.y * X2a[5]  + a1.z * X2a[6]  + a1.w * X2a[7]
                      + a2.x * X2a[8]  + a2.y * X2a[9]  + a2.z * X2a[10] + a2.w * X2a[11]
                      + a3.x * X2a[12] + a3.y * X2a[13] + a3.z * X2a[14] + a3.w * X2a[15];
                } else {
                    p = a0.x * X2b[0]  + a0.y * X2b[1]  + a0.z * X2b[2]  + a0.w * X2b[3]
                      + a1.x * X2b[4]  + a1.y * X2b[5]  + a1.z * X2b[6]  + a1.w * X2b[7]
                      + a2.x * X2b[8]  + a2.y * X2b[9]  + a2.z * X2b[10] + a2.w * X2b[11]
                      + a3.x * X2b[12] + a3.y * X2b[13] + a3.z * X2b[14] + a3.w * X2b[15];
                }
                p += __shfl_xor_sync(0xffffffffu, p, 16);
                if (lane < 16) red_add_f32(&g_agg[d * D_NN + lane], p);
            }
            __syncwarp();
        }
    }
}

// ---------------- K4: cooperative node transform (16 threads/node) ----------------
__global__ void k_node1(const float* __restrict__ x, const float* __restrict__ Wroot,
                        const float* __restrict__ be, const float* __restrict__ bconv,
                        const float* __restrict__ Wgat,
                        const float* __restrict__ a_src, const float* __restrict__ a_dst) {
    int tid = threadIdx.x;
    int n = blockIdx.x * 8 + (tid >> 4);   // exact grid
    int j = tid & 15;
    __shared__ float sh[128];

    float xj = __ldg(&x[n * D_IN + j]);
    float a = g_agg[n * D_NN + j] + __ldg(&bconv[j]);
#pragma unroll
    for (int i = 0; i < D_IN; i++)
        a += __shfl_sync(0xffffffffu, xj, i, 16) *
             (__ldg(&Wroot[i * D_NN + j]) + __ldg(&be[i * D_NN + j]));
    float hj = fmaxf(a, 0.f);
    sh[tid] = hj;
    __syncwarp();
    const float* shh = &sh[tid & ~15];

    float4 hp4 = make_float4(0.f, 0.f, 0.f, 0.f);
#pragma unroll
    for (int i = 0; i < D_NN; i++) {
        float hv = shh[i];
        float4 wg = *reinterpret_cast<const float4*>(&Wgat[i * D_GAT + j * 4]);
        hp4.x += hv * wg.x; hp4.y += hv * wg.y; hp4.z += hv * wg.z; hp4.w += hv * wg.w;
    }
    *reinterpret_cast<float4*>(&g_hp[(size_t)n * D_GAT + j * 4]) = hp4;

    float4 as = *reinterpret_cast<const float4*>(&a_src[j * 4]);
    float4 ad = *reinterpret_cast<const float4*>(&a_dst[j * 4]);
    float ss = hp4.x * as.x + hp4.y * as.y + hp4.z * as.z + hp4.w * as.w;
    float sd = hp4.x * ad.x + hp4.y * ad.y + hp4.z * ad.z + hp4.w * ad.w;
#pragma unroll
    for (int off = 8; off >= 1; off >>= 1) {
        ss += __shfl_xor_sync(0xffffffffu, ss, off, 16);
        sd += __shfl_xor_sync(0xffffffffu, sd, off, 16);
    }
    if (j == 0) {
        g_scs[n] = ss;
        g_scd[n] = sd;
        g_eself[n] = lrelu(ss + sd);
    }
}

// ---------------- K5: GAT softmax per dst node (warp/node, no atomics) ----------------
__global__ void k_softmax() {
    int n = blockIdx.x * 8 + (threadIdx.x >> 5);   // exact grid
    int lane = threadIdx.x & 31;
    int beg = g_rp_dst[n], end = g_rp_dst[n + 1];
    float scd_n = g_scd[n];
    float eself = g_eself[n];

    float m = eself;
    for (int j = beg + lane; j < end; j += 32) {
        float ev = lrelu(g_scs[g_de_s[j]] + scd_n);
        g_ev[j] = ev;
        m = fmaxf(m, ev);
    }
#pragma unroll
    for (int off = 16; off >= 1; off >>= 1)
        m = fmaxf(m, __shfl_xor_sync(0xffffffffu, m, off));

    float sum = 0.f;
    for (int j = beg + lane; j < end; j += 32) {
        float ex = __expf(g_ev[j] - m);
        g_ev[j] = ex;
        sum += ex;
    }
    float exs = __expf(eself - m);
    if (lane == 0) sum += exs;
#pragma unroll
    for (int off = 16; off >= 1; off >>= 1)
        sum += __shfl_xor_sync(0xffffffffu, sum, off);
    if (lane == 0) {
        g_selfw[n] = exs;
        g_invden[n] = 1.f / sum;
    }
}

// ---------------- K6: GAT aggregate + bias/relu + mean-pool scatter (16 threads/node) ----------------
__global__ void k_gatagg(const int* __restrict__ bids, const float* __restrict__ bgat) {
    int tid = threadIdx.x;
    int n = blockIdx.x * 16 + (tid >> 4);   // exact grid
    int og = tid & 15;
    float inv = g_invden[n];
    float w0 = g_selfw[n] * inv;
    float4 acc = *reinterpret_cast<const float4*>(&g_hp[(size_t)n * D_GAT + og * 4]);
    acc.x *= w0; acc.y *= w0; acc.z *= w0; acc.w *= w0;
    int beg = g_rp_dst[n], end = g_rp_dst[n + 1];
    for (int j = beg; j < end; j++) {
        int s = g_de_s[j];
        float w = g_ev[j] * inv;
        float4 v = *reinterpret_cast<const float4*>(&g_hp[(size_t)s * D_GAT + og * 4]);
        acc.x += w * v.x; acc.y += w * v.y; acc.z += w * v.z; acc.w += w * v.w;
    }
    float4 b = *reinterpret_cast<const float4*>(&bgat[og * 4]);
    acc.x = fmaxf(acc.x + b.x, 0.f); acc.y = fmaxf(acc.y + b.y, 0.f);
    acc.z = fmaxf(acc.z + b.z, 0.f); acc.w = fmaxf(acc.w + b.w, 0.f);
    int g = bids[n];
    red_add_v4(&g_pooled[g * D_GAT + og * 4], acc);
    if (og == 0) atomicAdd(&g_cnt[g], 1.f);
}

// ---------------- K7: MLP head, one block per graph ----------------
__global__ void k_head(const float* __restrict__ Wfc1, const float* __restrict__ bfc1,
                       const float* __restrict__ Wfc2, const float* __restrict__ bfc2,
                       float* __restrict__ out) {
    int g = blockIdx.x;
    int h = threadIdx.x;
    __shared__ float sp[D_GAT];
    __shared__ float red[HID];
    if (h < D_GAT) {
        float c = fmaxf(g_cnt[g], 1.f);
        sp[h] = g_pooled[g * D_GAT + h] / c;
    }
    __syncthreads();
    float acc = __ldg(&bfc1[h]);
#pragma unroll 8
    for (int k = 0; k < D_GAT; k++) acc += sp[k] * __ldg(&Wfc1[k * HID + h]);
    acc = fmaxf(acc, 0.f);
    red[h] = acc * __ldg(&Wfc2[h]);
    __syncthreads();
    for (int s = HID / 2; s > 0; s >>= 1) {
        if (h < s) red[h] += red[h + s];
        __syncthreads();
    }
    if (h == 0) out[g] = red[0] + __ldg(&bfc2[0]);
}

// ---------------- launch ----------------
extern "C" void kernel_launch(void* const* d_in, const int* in_sizes, int n_in,
                              void* d_out, int out_size) {
    const float* x     = (const float*)d_in[0];
    const int*   ei    = (const int*)d_in[1];     // int32 (JAX x64 disabled)
    const float* ea    = (const float*)d_in[2];
    const int*   bids  = (const int*)d_in[3];     // int32
    const float* We    = (const float*)d_in[4];
    const float* be    = (const float*)d_in[5];
    const float* Wroot = (const float*)d_in[6];
    const float* bconv = (const float*)d_in[7];
    const float* Wgat  = (const float*)d_in[8];
    const float* a_src = (const float*)d_in[9];
    const float* a_dst = (const float*)d_in[10];
    const float* bgat  = (const float*)d_in[11];
    const float* Wfc1  = (const float*)d_in[12];
    const float* bfc1  = (const float*)d_in[13];
    const float* Wfc2  = (const float*)d_in[14];
    const float* bfc2  = (const float*)d_in[15];
    float* out = (float*)d_out;

    k_hist<<<256, 256>>>(ei, We);                       // idx 0
    k_scan<<<2, 1024>>>();                              // idx 1
    k_scatter<<<(N_EDGES / 2 + 255) / 256, 256>>>(ei);  // idx 2
    k_nnconv<<<(N_NODES / 2 * 32 + 255) / 256, 256>>>(x, ea);   // idx 3 (profiled)
    k_node1<<<N_NODES / 8, 128>>>(x, Wroot, be, bconv, Wgat, a_src, a_dst);
    k_softmax<<<N_NODES / 8, 256>>>();
    k_gatagg<<<N_NODES / 16, 256>>>(bids, bgat);
    k_head<<<N_GRAPHS, HID>>>(Wfc1, bfc1, Wfc2, bfc2, out);
}

// round 11
// speedup vs baseline: 1.0759x; 1.0759x over previous
#include <cuda_runtime.h>

#define N_NODES  20000
#define N_EDGES  320000
#define F_EDGE   32
#define D_IN     16
#define D_NN     16
#define D_GAT    64
#define HID      128
#define N_GRAPHS 64
#define NEG_SLOPE 0.2f

// ---------------- scratch (zero-initialized at load; hist self-cleaned by k_scan) ----------------
static __device__ __align__(16) float g_WeT[F_EDGE * D_IN * D_NN];   // WeT[f][o][i]
static __device__ __align__(16) float g_agg[N_NODES * D_NN];
static __device__ __align__(16) float g_hp[N_NODES * D_GAT];
static __device__ __align__(16) float g_pooled[N_GRAPHS * D_GAT];
static __device__ float g_scs[N_NODES];
static __device__ float g_scd[N_NODES];
static __device__ float g_eself[N_NODES];
static __device__ float g_selfw[N_NODES];
static __device__ float g_invden[N_NODES];
static __device__ float g_cnt[N_GRAPHS];
// sorting scratch
static __device__ int g_hist_src[N_NODES], g_hist_dst[N_NODES];
static __device__ int g_rp_src[N_NODES + 1], g_rp_dst[N_NODES + 1];
static __device__ int g_cur_src[N_NODES], g_cur_dst[N_NODES];
static __device__ __align__(8) int2 g_se_ed[N_EDGES];  // by-src order: (edge id, dst)
static __device__ int g_de_s[N_EDGES];                 // by-dst order: src ids
static __device__ float g_ev[N_EDGES];                 // softmax buffer

// ---------------- helpers ----------------
__device__ __forceinline__ void red_add_v4(float* p, float4 v) {
    asm volatile("red.global.add.v4.f32 [%0], {%1,%2,%3,%4};"
                 :: "l"(p), "f"(v.x), "f"(v.y), "f"(v.z), "f"(v.w) : "memory");
}
__device__ __forceinline__ void red_add_f32(float* p, float v) {
    asm volatile("red.global.add.f32 [%0], %1;" :: "l"(p), "f"(v) : "memory");
}
__device__ __forceinline__ float lrelu(float v) { return v > 0.f ? v : NEG_SLOPE * v; }

// ---------------- K0: histograms + WeT transpose + zero accumulators (fused) ----------------
__global__ void k_hist(const int* __restrict__ ei, const float* __restrict__ We) {
    int t = blockIdx.x * blockDim.x + threadIdx.x;
    int stride = gridDim.x * blockDim.x;
    for (int i = t; i < F_EDGE * D_IN * D_NN; i += stride) {
        int f = i >> 8, r = i & 255, o = r >> 4, ii = r & 15;
        g_WeT[(f << 8) + (o << 4) + ii] = We[(f << 8) + (ii << 4) + o];
    }
    for (int i = t; i < N_NODES * D_NN; i += stride) g_agg[i] = 0.f;
    for (int i = t; i < N_GRAPHS * D_GAT; i += stride) g_pooled[i] = 0.f;
    for (int i = t; i < N_GRAPHS; i += stride) g_cnt[i] = 0.f;
    for (int e = t; e < N_EDGES; e += stride) {
        atomicAdd(&g_hist_src[ei[e]], 1);
        atomicAdd(&g_hist_dst[ei[N_EDGES + e]], 1);
    }
}

// ---------------- K1: exclusive scan of both histograms (shfl-based, self-cleans hist) ----------------
#define SCAN_CHUNK 20
__global__ void k_scan() {
    int* hist = (blockIdx.x == 0) ? g_hist_src : g_hist_dst;
    int* rp   = (blockIdx.x == 0) ? g_rp_src   : g_rp_dst;
    int* cur  = (blockIdx.x == 0) ? g_cur_src  : g_cur_dst;
    __shared__ int wsum[32];
    int tid = threadIdx.x;
    int lane = tid & 31, wid = tid >> 5;
    int base = tid * SCAN_CHUNK;
    int local[SCAN_CHUNK];
    int s = 0;
#pragma unroll
    for (int k = 0; k < SCAN_CHUNK; k++) {
        int idx = base + k;
        int v = 0;
        if (idx < N_NODES) { v = hist[idx]; hist[idx] = 0; }   // read + self-clean
        local[k] = s; s += v;
    }
    int sc = s;
#pragma unroll
    for (int off = 1; off < 32; off <<= 1) {
        int tv = __shfl_up_sync(0xffffffffu, sc, off);
        if (lane >= off) sc += tv;
    }
    if (lane == 31) wsum[wid] = sc;
    __syncthreads();
    if (wid == 0) {
        int v = wsum[lane];
#pragma unroll
        for (int off = 1; off < 32; off <<= 1) {
            int tv = __shfl_up_sync(0xffffffffu, v, off);
            if (lane >= off) v += tv;
        }
        wsum[lane] = v;
    }
    __syncthreads();
    int offset = sc - s + (wid > 0 ? wsum[wid - 1] : 0);   // exclusive prefix of this thread
#pragma unroll
    for (int k = 0; k < SCAN_CHUNK; k++) {
        int idx = base + k;
        if (idx < N_NODES) { rp[idx] = offset + local[k]; cur[idx] = offset + local[k]; }
    }
    if (tid == 1023) rp[N_NODES] = offset + s;
}

// ---------------- K2: scatter into both sorted orders (2 edges/thread for ILP) ----------------
__global__ void k_scatter(const int* __restrict__ ei) {
    int t = blockIdx.x * blockDim.x + threadIdx.x;
    int e0 = 2 * t, e1 = 2 * t + 1;
    if (e0 >= N_EDGES) return;
    int s0 = ei[e0], d0 = ei[N_EDGES + e0];
    int s1 = 0, d1 = 0;
    bool has1 = (e1 < N_EDGES);
    if (has1) { s1 = ei[e1]; d1 = ei[N_EDGES + e1]; }
    int p0 = atomicAdd(&g_cur_src[s0], 1);
    int q0 = atomicAdd(&g_cur_dst[d0], 1);
    int p1 = 0, q1 = 0;
    if (has1) {
        p1 = atomicAdd(&g_cur_src[s1], 1);
        q1 = atomicAdd(&g_cur_dst[d1], 1);
    }
    g_se_ed[p0] = make_int2(e0, d0);
    g_de_s[q0] = s0;
    if (has1) {
        g_se_ed[p1] = make_int2(e1, d1);
        g_de_s[q1] = s1;
    }
}

// ---------------- K3 (profiled slot): NNConv — warp per 2 src nodes, X2 register-resident ----------------
// v5: tree-partial dot (4 independent 4-FFMA chains) + launch_bounds(256,3) for 3 blocks/SM.
#define EA_CHUNK 8
__global__ void __launch_bounds__(256, 3) k_nnconv(const float* __restrict__ x,
                                                   const float* __restrict__ ea) {
    __shared__ __align__(16) float s_ea[8][EA_CHUNK][F_EDGE];   // 8 KB
    int w = (blockIdx.x * blockDim.x + threadIdx.x) >> 5;  // warp id < 10000
    int wl = threadIdx.x >> 5;
    int lane = threadIdx.x & 31;
    int g = lane >> 4, o = lane & 15;

    int n0 = 2 * w, n1 = 2 * w + 1;
    float X2a[16], X2b[16];
    {
        float4 xa[4], xb[4];
#pragma unroll
        for (int c = 0; c < 4; c++) {
            xa[c] = *reinterpret_cast<const float4*>(&x[n0 * D_IN + c * 4]);
            xb[c] = *reinterpret_cast<const float4*>(&x[n1 * D_IN + c * 4]);
        }
#pragma unroll
        for (int k = 0; k < 16; k++) {
            const float4* wt = reinterpret_cast<const float4*>(
                &g_WeT[((16 * g + k) << 8) + (o << 4)]);
            float4 w0 = wt[0], w1 = wt[1], w2 = wt[2], w3 = wt[3];
            float sa0 = w0.x * xa[0].x + w0.y * xa[0].y + w0.z * xa[0].z + w0.w * xa[0].w;
            float sa1 = w1.x * xa[1].x + w1.y * xa[1].y + w1.z * xa[1].z + w1.w * xa[1].w;
            float sa2 = w2.x * xa[2].x + w2.y * xa[2].y + w2.z * xa[2].z + w2.w * xa[2].w;
            float sa3 = w3.x * xa[3].x + w3.y * xa[3].y + w3.z * xa[3].z + w3.w * xa[3].w;
            float sb0 = w0.x * xb[0].x + w0.y * xb[0].y + w0.z * xb[0].z + w0.w * xb[0].w;
            float sb1 = w1.x * xb[1].x + w1.y * xb[1].y + w1.z * xb[1].z + w1.w * xb[1].w;
            float sb2 = w2.x * xb[2].x + w2.y * xb[2].y + w2.z * xb[2].z + w2.w * xb[2].w;
            float sb3 = w3.x * xb[3].x + w3.y * xb[3].y + w3.z * xb[3].z + w3.w * xb[3].w;
            X2a[k] = (sa0 + sa1) + (sa2 + sa3);
            X2b[k] = (sb0 + sb1) + (sb2 + sb3);
        }
    }

#pragma unroll
    for (int half = 0; half < 2; half++) {
        int n = half ? n1 : n0;
        int beg = g_rp_src[n], end = g_rp_src[n + 1];
        for (int base = beg; base < end; base += EA_CHUNK) {
            int nleft = min(EA_CHUNK, end - base);
            // stage ea rows for up to 8 edges (2 coalesced rounds)
#pragma unroll
            for (int r = 0; r < 2; r++) {
                int item = lane + 32 * r;         // 0..63
                int i = item >> 3, c = item & 7;
                if (i < nleft) {
                    int e = g_se_ed[base + i].x;
                    *reinterpret_cast<float4*>(&s_ea[wl][i][c * 4]) =
                        *reinterpret_cast<const float4*>(&ea[(size_t)e * F_EDGE + c * 4]);
                }
            }
            __syncwarp();
#pragma unroll 2
            for (int i = 0; i < nleft; i++) {
                int d = g_se_ed[base + i].y;   // broadcast, L1-hot
                const float4* ar = reinterpret_cast<const float4*>(&s_ea[wl][i][g * 16]);
                float4 a0 = ar[0], a1 = ar[1], a2 = ar[2], a3 = ar[3];
                float q0, q1, q2, q3;
                if (half == 0) {
                    q0 = a0.x * X2a[0]  + a0.y * X2a[1]  + a0.z * X2a[2]  + a0.w * X2a[3];
                    q1 = a1.x * X2a[4]  + a1.y * X2a[5]  + a1.z * X2a[6]  + a1.w * X2a[7];
                    q2 = a2.x * X2a[8]  + a2.y * X2a[9]  + a2.z * X2a[10] + a2.w * X2a[11];
                    q3 = a3.x * X2a[12] + a3.y * X2a[13] + a3.z * X2a[14] + a3.w * X2a[15];
                } else {
                    q0 = a0.x * X2b[0]  + a0.y * X2b[1]  + a0.z * X2b[2]  + a0.w * X2b[3];
                    q1 = a1.x * X2b[4]  + a1.y * X2b[5]  + a1.z * X2b[6]  + a1.w * X2b[7];
                    q2 = a2.x * X2b[8]  + a2.y * X2b[9]  + a2.z * X2b[10] + a2.w * X2b[11];
                    q3 = a3.x * X2b[12] + a3.y * X2b[13] + a3.z * X2b[14] + a3.w * X2b[15];
                }
                float p = (q0 + q1) + (q2 + q3);
                p += __shfl_xor_sync(0xffffffffu, p, 16);
                if (lane < 16) red_add_f32(&g_agg[d * D_NN + lane], p);
            }
            __syncwarp();
        }
    }
}

// ---------------- K4: cooperative node transform (16 threads/node) ----------------
__global__ void k_node1(const float* __restrict__ x, const float* __restrict__ Wroot,
                        const float* __restrict__ be, const float* __restrict__ bconv,
                        const float* __restrict__ Wgat,
                        const float* __restrict__ a_src, const float* __restrict__ a_dst) {
    int tid = threadIdx.x;
    int n = blockIdx.x * 8 + (tid >> 4);   // exact grid
    int j = tid & 15;
    __shared__ float sh[128];

    float xj = __ldg(&x[n * D_IN + j]);
    float a = g_agg[n * D_NN + j] + __ldg(&bconv[j]);
#pragma unroll
    for (int i = 0; i < D_IN; i++)
        a += __shfl_sync(0xffffffffu, xj, i, 16) *
             (__ldg(&Wroot[i * D_NN + j]) + __ldg(&be[i * D_NN + j]));
    float hj = fmaxf(a, 0.f);
    sh[tid] = hj;
    __syncwarp();
    const float* shh = &sh[tid & ~15];

    float4 hp4 = make_float4(0.f, 0.f, 0.f, 0.f);
#pragma unroll
    for (int i = 0; i < D_NN; i++) {
        float hv = shh[i];
        float4 wg = *reinterpret_cast<const float4*>(&Wgat[i * D_GAT + j * 4]);
        hp4.x += hv * wg.x; hp4.y += hv * wg.y; hp4.z += hv * wg.z; hp4.w += hv * wg.w;
    }
    *reinterpret_cast<float4*>(&g_hp[(size_t)n * D_GAT + j * 4]) = hp4;

    float4 as = *reinterpret_cast<const float4*>(&a_src[j * 4]);
    float4 ad = *reinterpret_cast<const float4*>(&a_dst[j * 4]);
    float ss = hp4.x * as.x + hp4.y * as.y + hp4.z * as.z + hp4.w * as.w;
    float sd = hp4.x * ad.x + hp4.y * ad.y + hp4.z * ad.z + hp4.w * ad.w;
#pragma unroll
    for (int off = 8; off >= 1; off >>= 1) {
        ss += __shfl_xor_sync(0xffffffffu, ss, off, 16);
        sd += __shfl_xor_sync(0xffffffffu, sd, off, 16);
    }
    if (j == 0) {
        g_scs[n] = ss;
        g_scd[n] = sd;
        g_eself[n] = lrelu(ss + sd);
    }
}

// ---------------- K5: GAT softmax per dst node (warp/node, no atomics) ----------------
__global__ void k_softmax() {
    int n = blockIdx.x * 8 + (threadIdx.x >> 5);   // exact grid
    int lane = threadIdx.x & 31;
    int beg = g_rp_dst[n], end = g_rp_dst[n + 1];
    float scd_n = g_scd[n];
    float eself = g_eself[n];

    float m = eself;
    for (int j = beg + lane; j < end; j += 32) {
        float ev = lrelu(g_scs[g_de_s[j]] + scd_n);
        g_ev[j] = ev;
        m = fmaxf(m, ev);
    }
#pragma unroll
    for (int off = 16; off >= 1; off >>= 1)
        m = fmaxf(m, __shfl_xor_sync(0xffffffffu, m, off));

    float sum = 0.f;
    for (int j = beg + lane; j < end; j += 32) {
        float ex = __expf(g_ev[j] - m);
        g_ev[j] = ex;
        sum += ex;
    }
    float exs = __expf(eself - m);
    if (lane == 0) sum += exs;
#pragma unroll
    for (int off = 16; off >= 1; off >>= 1)
        sum += __shfl_xor_sync(0xffffffffu, sum, off);
    if (lane == 0) {
        g_selfw[n] = exs;
        g_invden[n] = 1.f / sum;
    }
}

// ---------------- K6: GAT aggregate + bias/relu + mean-pool scatter (16 threads/node) ----------------
__global__ void k_gatagg(const int* __restrict__ bids, const float* __restrict__ bgat) {
    int tid = threadIdx.x;
    int n = blockIdx.x * 16 + (tid >> 4);   // exact grid
    int og = tid & 15;
    float inv = g_invden[n];
    float w0 = g_selfw[n] * inv;
    float4 acc = *reinterpret_cast<const float4*>(&g_hp[(size_t)n * D_GAT + og * 4]);
    acc.x *= w0; acc.y *= w0; acc.z *= w0; acc.w *= w0;
    int beg = g_rp_dst[n], end = g_rp_dst[n + 1];
    for (int j = beg; j < end; j++) {
        int s = g_de_s[j];
        float w = g_ev[j] * inv;
        float4 v = *reinterpret_cast<const float4*>(&g_hp[(size_t)s * D_GAT + og * 4]);
        acc.x += w * v.x; acc.y += w * v.y; acc.z += w * v.z; acc.w += w * v.w;
    }
    float4 b = *reinterpret_cast<const float4*>(&bgat[og * 4]);
    acc.x = fmaxf(acc.x + b.x, 0.f); acc.y = fmaxf(acc.y + b.y, 0.f);
    acc.z = fmaxf(acc.z + b.z, 0.f); acc.w = fmaxf(acc.w + b.w, 0.f);
    int g = bids[n];
    red_add_v4(&g_pooled[g * D_GAT + og * 4], acc);
    if (og == 0) atomicAdd(&g_cnt[g], 1.f);
}

// ---------------- K7: MLP head, one block per graph ----------------
__global__ void k_head(const float* __restrict__ Wfc1, const float* __restrict__ bfc1,
                       const float* __restrict__ Wfc2, const float* __restrict__ bfc2,
                       float* __restrict__ out) {
    int g = blockIdx.x;
    int h = threadIdx.x;
    __shared__ float sp[D_GAT];
    __shared__ float red[HID];
    if (h < D_GAT) {
        float c = fmaxf(g_cnt[g], 1.f);
        sp[h] = g_pooled[g * D_GAT + h] / c;
    }
    __syncthreads();
    float acc = __ldg(&bfc1[h]);
#pragma unroll 8
    for (int k = 0; k < D_GAT; k++) acc += sp[k] * __ldg(&Wfc1[k * HID + h]);
    acc = fmaxf(acc, 0.f);
    red[h] = acc * __ldg(&Wfc2[h]);
    __syncthreads();
    for (int s = HID / 2; s > 0; s >>= 1) {
        if (h < s) red[h] += red[h + s];
        __syncthreads();
    }
    if (h == 0) out[g] = red[0] + __ldg(&bfc2[0]);
}

// ---------------- launch ----------------
extern "C" void kernel_launch(void* const* d_in, const int* in_sizes, int n_in,
                              void* d_out, int out_size) {
    const float* x     = (const float*)d_in[0];
    const int*   ei    = (const int*)d_in[1];     // int32 (JAX x64 disabled)
    const float* ea    = (const float*)d_in[2];
    const int*   bids  = (const int*)d_in[3];     // int32
    const float* We    = (const float*)d_in[4];
    const float* be    = (const float*)d_in[5];
    const float* Wroot = (const float*)d_in[6];
    const float* bconv = (const float*)d_in[7];
    const float* Wgat  = (const float*)d_in[8];
    const float* a_src = (const float*)d_in[9];
    const float* a_dst = (const float*)d_in[10];
    const float* bgat  = (const float*)d_in[11];
    const float* Wfc1  = (const float*)d_in[12];
    const float* bfc1  = (const float*)d_in[13];
    const float* Wfc2  = (const float*)d_in[14];
    const float* bfc2  = (const float*)d_in[15];
    float* out = (float*)d_out;

    k_hist<<<256, 256>>>(ei, We);                       // idx 0
    k_scan<<<2, 1024>>>();                              // idx 1
    k_scatter<<<(N_EDGES / 2 + 255) / 256, 256>>>(ei);  // idx 2
    k_nnconv<<<(N_NODES / 2 * 32 + 255) / 256, 256>>>(x, ea);   // idx 3 (profiled)
    k_node1<<<N_NODES / 8, 128>>>(x, Wroot, be, bconv, Wgat, a_src, a_dst);
    k_softmax<<<N_NODES / 8, 256>>>();
    k_gatagg<<<N_NODES / 16, 256>>>(bids, bgat);
    k_head<<<N_GRAPHS, HID>>>(Wfc1, bfc1, Wfc2, bfc2, out);
}